// round 7
// baseline (speedup 1.0000x reference)
#include <cuda_runtime.h>
#include <cstdint>
#include <cstddef>

// ---------------- problem constants ----------------
#define DD     1024
#define PCOLS  405       // 1 + 80 + 324
#define NTILE  4
#define BNL    104       // live cols per tile
#define BNP    112       // padded rows per tile (14 n8 blocks)
#define NF     300
#define BM     256
#define BK     32
#define NCHUNK (DD / BK)

#define A_BYTES  (BM * 128)              // 32768
#define B_BYTES  (BNP * 128)             // 14336
#define STAGE_SZ (A_BYTES + B_BYTES)     // 47104
#define SMEM_DYN (1024 + 2 * STAGE_SZ)   // 95232 -> 2 CTAs/SM
#define LDC      120

// ---------------- device scratch ----------------
__device__ float g_Wt[(size_t)NTILE * BNP * DD];
__device__ float g_bias[NTILE * BNP];

__device__ __forceinline__ float to_tf32(float f) {
    float r; asm("cvt.rna.tf32.f32 %0, %1;" : "=f"(r) : "f"(f)); return r;
}
__device__ __forceinline__ uint32_t smem_u32(const void* p) {
    uint32_t a;
    asm("{ .reg .u64 t; cvta.to.shared.u64 t, %1; cvt.u32.u64 %0, t; }" : "=r"(a) : "l"(p));
    return a;
}
__device__ __forceinline__ void cpa16(uint32_t dst, const void* src) {
    asm volatile("cp.async.cg.shared.global [%0], [%1], 16;" :: "r"(dst), "l"(src));
}
__device__ __forceinline__ void ldsm4(uint32_t r[4], uint32_t addr) {
    asm volatile("ldmatrix.sync.aligned.m8n8.x4.shared.b16 {%0,%1,%2,%3}, [%4];"
        : "=r"(r[0]), "=r"(r[1]), "=r"(r[2]), "=r"(r[3]) : "r"(addr));
}
__device__ __forceinline__ void mma8(float d[4], const uint32_t a[4], uint32_t b0, uint32_t b1) {
    asm volatile(
        "mma.sync.aligned.m16n8k8.row.col.f32.tf32.tf32.f32 "
        "{%0,%1,%2,%3}, {%4,%5,%6,%7}, {%8,%9}, {%0,%1,%2,%3};"
        : "+f"(d[0]), "+f"(d[1]), "+f"(d[2]), "+f"(d[3])
        : "r"(a[0]), "r"(a[1]), "r"(a[2]), "r"(a[3]), "r"(b0), "r"(b1));
}

// ---------------- prep: fused W rows (tf32-pre-rounded) + bias, norm inlined ----------------
__global__ void k_prep(const float* __restrict__ Wcls, const float* __restrict__ bcls,
                       const float* __restrict__ Wsem, const float* __restrict__ bsem,
                       const float* __restrict__ Wbb,  const float* __restrict__ bbb,
                       const float* __restrict__ semm) {
    __shared__ float srow[NF];
    __shared__ float ws[8];
    const int b = blockIdx.x, t = threadIdx.x;
    const int tile = b / BNP, r = b % BNP;
    const int j = tile * BNL + r;
    float* wo = g_Wt + (size_t)b * DD;

    if (r >= BNL || j >= PCOLS) {
        for (int d = t; d < DD; d += 256) wo[d] = 0.f;
        if (t == 0) g_bias[b] = 0.f;
        return;
    }
    if (j == 0) {
        for (int d = t; d < DD; d += 256) wo[d] = to_tf32(Wcls[d]);
        if (t == 0) g_bias[b] = bcls[0];
    } else if (j <= 80) {
        const int c = j - 1;
        float ss = 0.f;
        for (int f = t; f < NF; f += 256) { float v = semm[c * NF + f]; ss += v * v; }
        for (int o = 16; o; o >>= 1) ss += __shfl_xor_sync(0xffffffffu, ss, o);
        if ((t & 31) == 0) ws[t >> 5] = ss;
        __syncthreads();
        float tot = 0.f;
#pragma unroll
        for (int i = 0; i < 8; i++) tot += ws[i];
        const float scale = 8.0f * rsqrtf(tot);
        for (int f = t; f < NF; f += 256) srow[f] = semm[c * NF + f] * scale;
        __syncthreads();
        float a0 = 0.f, a1 = 0.f, a2 = 0.f, a3 = 0.f;
        for (int f = 0; f < NF; f++) {
            float s = srow[f];
            const float* wp = Wsem + (size_t)f * DD + t;
            a0 += s * wp[0]; a1 += s * wp[256]; a2 += s * wp[512]; a3 += s * wp[768];
        }
        wo[t] = to_tf32(a0); wo[t + 256] = to_tf32(a1);
        wo[t + 512] = to_tf32(a2); wo[t + 768] = to_tf32(a3);
        if (t == 0) {
            float bb = 0.f;
            for (int f = 0; f < NF; f++) bb += srow[f] * bsem[f];
            g_bias[b] = bb;
        }
    } else {
        const int i = j - 81;
        for (int d = t; d < DD; d += 256) wo[d] = to_tf32(Wbb[(size_t)i * DD + d]);
        if (t == 0) g_bias[b] = bbb[i];
    }
}

// ---------------- main GEMM: BM=256, 512 thr, raw mma.tf32 + ldmatrix, 2-stage ----------------
__device__ __forceinline__ void issue_stage(uint32_t sbase, const float* __restrict__ xrow0,
                                            const float* __restrict__ wrow0, int c, int tid) {
    const float* xs = xrow0 + c * BK;
    const float* ws = wrow0 + c * BK;
#pragma unroll
    for (int i = 0; i < 4; i++) {               // A: 256 rows x 8 quads = 2048
        int seg = tid + i * 512;
        int row = seg >> 3, q = seg & 7;
        cpa16(sbase + (uint32_t)(row * 128 + ((q ^ (row & 7)) << 4)),
              xs + (size_t)row * DD + q * 4);
    }
#pragma unroll
    for (int i = 0; i < 2; i++) {               // B: 112 rows x 8 quads = 896
        int seg = tid + i * 512;
        if (seg < BNP * 8) {
            int row = seg >> 3, q = seg & 7;
            cpa16(sbase + (uint32_t)(A_BYTES + row * 128 + ((q ^ (row & 7)) << 4)),
                  ws + (size_t)row * DD + q * 4);
        }
    }
    asm volatile("cp.async.commit_group;" ::: "memory");
}

__global__ __launch_bounds__(512, 2) void k_main(const float* __restrict__ x,
                                                 float* __restrict__ out, int N) {
    extern __shared__ char sm[];
    const int tid = threadIdx.x, wid = tid >> 5, lane = tid & 31;
    const int warp_m = wid & 7;        // 8 in M: 32 rows each
    const int warp_n = wid >> 3;       // 2 in N: w0 cols 0-63 (8 blk), w1 cols 64-111 (6 blk)
    const int nt = blockIdx.x;
    const size_t row0 = (size_t)blockIdx.y * BM;
    const size_t NS = (size_t)N * 81;

    const int livecols = min(BNL, PCOLS - nt * BNL);          // 104 or 93
    const int liveblk  = (livecols + 7) >> 3;                 // 13 or 12
    const int njw = warp_n ? min(6, liveblk - 8) : 8;         // live n8 blocks this warp
    const int ngrp = warp_n ? 3 : 4;                          // ldsm.x4 groups

    float* sBias = (float*)sm;
    for (int i = tid; i < BNP; i += 512) sBias[i] = g_bias[nt * BNP + i];

    uint32_t st0 = smem_u32(sm + 1024);
    uint32_t st1 = st0 + STAGE_SZ;

    const float* xrow0 = x + row0 * DD;
    const float* wrow0 = g_Wt + (size_t)nt * BNP * DD;

    // ldmatrix source rows (fixed across k)
    int rA[2], rB[4];
    const int qbA = (lane >> 4) & 1;
    const int qbB = (lane >> 3) & 1;
#pragma unroll
    for (int mi = 0; mi < 2; mi++)
        rA[mi] = warp_m * 32 + mi * 16 + ((lane >> 3) & 1) * 8 + (lane & 7);
#pragma unroll
    for (int g = 0; g < 4; g++)
        rB[g] = warp_n * 64 + g * 16 + ((lane >> 4) & 1) * 8 + (lane & 7);

    float acc[2][8][4];
#pragma unroll
    for (int mi = 0; mi < 2; mi++)
#pragma unroll
        for (int nj = 0; nj < 8; nj++)
#pragma unroll
            for (int e = 0; e < 4; e++) acc[mi][nj][e] = 0.f;

    issue_stage(st0, xrow0, wrow0, 0, tid);
    issue_stage(st1, xrow0, wrow0, 1, tid);

    for (int c = 0; c < NCHUNK; c++) {
        uint32_t sb = (c & 1) ? st1 : st0;
        if (c == NCHUNK - 1) asm volatile("cp.async.wait_group 0;" ::: "memory");
        else                 asm volatile("cp.async.wait_group 1;" ::: "memory");
        __syncthreads();

        const uint32_t Ab = sb, Bb = sb + A_BYTES;
#pragma unroll
        for (int kq2 = 0; kq2 < 4; kq2++) {
            uint32_t a[2][4];
#pragma unroll
            for (int mi = 0; mi < 2; mi++) {
                int r = rA[mi];
                ldsm4(a[mi], Ab + (uint32_t)(r * 128 + (((2 * kq2 + qbA) ^ (r & 7)) << 4)));
            }
            uint32_t b[4][4];
#pragma unroll
            for (int g = 0; g < 4; g++) {
                if (g < ngrp) {
                    int r = rB[g];
                    ldsm4(b[g], Bb + (uint32_t)(r * 128 + (((2 * kq2 + qbB) ^ (r & 7)) << 4)));
                }
            }
#pragma unroll
            for (int mi = 0; mi < 2; mi++)
#pragma unroll
                for (int nj = 0; nj < 8; nj++)
                    if (nj < njw)
                        mma8(acc[mi][nj], a[mi], b[nj >> 1][(nj & 1) * 2], b[nj >> 1][(nj & 1) * 2 + 1]);
        }
        __syncthreads();
        if (c + 2 < NCHUNK)
            issue_stage(sb, xrow0, wrow0, c + 2, tid);
    }

    // ---- epilogue: two 128-row halves through smem ----
    float* sC = (float*)(sm + 1024);
    float* outb = out + NS;
    const int tr = lane >> 2, tc2 = (lane & 3) * 2;
    const int jbase = nt * BNL;
#pragma unroll
    for (int half = 0; half < 2; half++) {
        __syncthreads();
        if ((warp_m >> 2) == half) {
            const int rb = (warp_m & 3) * 32;
#pragma unroll
            for (int mi = 0; mi < 2; mi++)
#pragma unroll
                for (int nj = 0; nj < 8; nj++)
                    if (nj < njw) {
                        int r = rb + mi * 16 + tr;
                        int cc = warp_n * 64 + nj * 8 + tc2;
                        *(float2*)&sC[r * LDC + cc]       = make_float2(acc[mi][nj][0], acc[mi][nj][1]);
                        *(float2*)&sC[(r + 8) * LDC + cc] = make_float2(acc[mi][nj][2], acc[mi][nj][3]);
                    }
        }
        __syncthreads();
        for (int e = tid; e < 128 * livecols; e += 512) {
            int row = e / livecols, n = e % livecols;
            int j = jbase + n;
            float v = sC[row * LDC + n] + sBias[n];
            size_t gr = row0 + half * 128 + row;
            if (j < 81) out[gr * 81 + j] = v;
            else        outb[gr * 324 + (j - 81)] = v;
        }
    }
}

// ---------------- launch ----------------
extern "C" void kernel_launch(void* const* d_in, const int* in_sizes, int n_in,
                              void* d_out, int out_size) {
    const float* x    = (const float*)d_in[0];
    const float* Wcls = (const float*)d_in[1];
    const float* bcls = (const float*)d_in[2];
    const float* Wsem = (const float*)d_in[3];
    const float* bsem = (const float*)d_in[4];
    const float* Wbb  = (const float*)d_in[5];
    const float* bbb  = (const float*)d_in[6];
    const float* semm = (const float*)d_in[7];
    float* out = (float*)d_out;
    int N = in_sizes[0] / DD;

    cudaFuncSetAttribute(k_main, cudaFuncAttributeMaxDynamicSharedMemorySize, SMEM_DYN);

    k_prep<<<NTILE * BNP, 256>>>(Wcls, bcls, Wsem, bsem, Wbb, bbb, semm);
    dim3 grid(NTILE, N / BM);
    k_main<<<grid, 512, SMEM_DYN>>>(x, out, N);
}

// round 8
// speedup vs baseline: 4.3578x; 4.3578x over previous
#include <cuda_runtime.h>
#include <cstdint>
#include <cstddef>

// ---------------- problem constants ----------------
#define DD     1024
#define PCOLS  405       // 1 + 80 + 324
#define NTILE  4
#define BNL    104       // live cols per tile
#define BNP    112       // padded rows per tile (14 n8 blocks)
#define NF     300
#define BM     256
#define BK     32
#define NCHUNK (DD / BK)
#define NSTAGE 4

#define A_BYTES  (BM * 128)              // 32768
#define B_BYTES  (BNP * 128)             // 14336
#define STAGE_SZ (A_BYTES + B_BYTES)     // 47104
#define SMEM_DYN (1024 + NSTAGE * STAGE_SZ)  // 189440 < 228KB, occ 1
#define LDC      120

// ---------------- device scratch ----------------
__device__ float g_Wt[(size_t)NTILE * BNP * DD];
__device__ float g_bias[NTILE * BNP];

__device__ __forceinline__ float to_tf32(float f) {
    float r; asm("cvt.rna.tf32.f32 %0, %1;" : "=f"(r) : "f"(f)); return r;
}
__device__ __forceinline__ uint32_t smem_u32(const void* p) {
    uint32_t a;
    asm("{ .reg .u64 t; cvta.to.shared.u64 t, %1; cvt.u32.u64 %0, t; }" : "=r"(a) : "l"(p));
    return a;
}
__device__ __forceinline__ void cpa16(uint32_t dst, const void* src) {
    asm volatile("cp.async.cg.shared.global [%0], [%1], 16;" :: "r"(dst), "l"(src));
}
__device__ __forceinline__ void ldsm4(uint32_t r[4], uint32_t addr) {
    asm volatile("ldmatrix.sync.aligned.m8n8.x4.shared.b16 {%0,%1,%2,%3}, [%4];"
        : "=r"(r[0]), "=r"(r[1]), "=r"(r[2]), "=r"(r[3]) : "r"(addr));
}
__device__ __forceinline__ void mma8(float d[4], const uint32_t a[4], uint32_t b0, uint32_t b1) {
    asm volatile(
        "mma.sync.aligned.m16n8k8.row.col.f32.tf32.tf32.f32 "
        "{%0,%1,%2,%3}, {%4,%5,%6,%7}, {%8,%9}, {%0,%1,%2,%3};"
        : "+f"(d[0]), "+f"(d[1]), "+f"(d[2]), "+f"(d[3])
        : "r"(a[0]), "r"(a[1]), "r"(a[2]), "r"(a[3]), "r"(b0), "r"(b1));
}

// ---------------- prep: fused W rows (tf32-pre-rounded) + bias, norm inlined ----------------
__global__ void k_prep(const float* __restrict__ Wcls, const float* __restrict__ bcls,
                       const float* __restrict__ Wsem, const float* __restrict__ bsem,
                       const float* __restrict__ Wbb,  const float* __restrict__ bbb,
                       const float* __restrict__ semm) {
    __shared__ float srow[NF];
    __shared__ float ws[8];
    const int b = blockIdx.x, t = threadIdx.x;
    const int tile = b / BNP, r = b % BNP;
    const int j = tile * BNL + r;
    float* wo = g_Wt + (size_t)b * DD;

    if (r >= BNL || j >= PCOLS) {
        for (int d = t; d < DD; d += 256) wo[d] = 0.f;
        if (t == 0) g_bias[b] = 0.f;
        return;
    }
    if (j == 0) {
        for (int d = t; d < DD; d += 256) wo[d] = to_tf32(Wcls[d]);
        if (t == 0) g_bias[b] = bcls[0];
    } else if (j <= 80) {
        const int c = j - 1;
        float ss = 0.f;
        for (int f = t; f < NF; f += 256) { float v = semm[c * NF + f]; ss += v * v; }
        for (int o = 16; o; o >>= 1) ss += __shfl_xor_sync(0xffffffffu, ss, o);
        if ((t & 31) == 0) ws[t >> 5] = ss;
        __syncthreads();
        float tot = 0.f;
#pragma unroll
        for (int i = 0; i < 8; i++) tot += ws[i];
        const float scale = 8.0f * rsqrtf(tot);
        for (int f = t; f < NF; f += 256) srow[f] = semm[c * NF + f] * scale;
        __syncthreads();
        float a0 = 0.f, a1 = 0.f, a2 = 0.f, a3 = 0.f;
        for (int f = 0; f < NF; f++) {
            float s = srow[f];
            const float* wp = Wsem + (size_t)f * DD + t;
            a0 += s * wp[0]; a1 += s * wp[256]; a2 += s * wp[512]; a3 += s * wp[768];
        }
        wo[t] = to_tf32(a0); wo[t + 256] = to_tf32(a1);
        wo[t + 512] = to_tf32(a2); wo[t + 768] = to_tf32(a3);
        if (t == 0) {
            float bb = 0.f;
            for (int f = 0; f < NF; f++) bb += srow[f] * bsem[f];
            g_bias[b] = bb;
        }
    } else {
        const int i = j - 81;
        for (int d = t; d < DD; d += 256) wo[d] = to_tf32(Wbb[(size_t)i * DD + d]);
        if (t == 0) g_bias[b] = bbb[i];
    }
}

// ---------------- main GEMM: BM=256, 512 thr, occ=1, 4-stage, 1 barrier/chunk ----------------
__device__ __forceinline__ void issue_stage(uint32_t sbase, const float* __restrict__ xrow0,
                                            const float* __restrict__ wrow0, int c, int tid) {
    const float* xs = xrow0 + c * BK;
    const float* ws = wrow0 + c * BK;
#pragma unroll
    for (int i = 0; i < 4; i++) {               // A: 256 rows x 8 quads = 2048
        int seg = tid + i * 512;
        int row = seg >> 3, q = seg & 7;
        cpa16(sbase + (uint32_t)(row * 128 + ((q ^ (row & 7)) << 4)),
              xs + (size_t)row * DD + q * 4);
    }
#pragma unroll
    for (int i = 0; i < 2; i++) {               // B: 112 rows x 8 quads = 896
        int seg = tid + i * 512;
        if (seg < BNP * 8) {
            int row = seg >> 3, q = seg & 7;
            cpa16(sbase + (uint32_t)(A_BYTES + row * 128 + ((q ^ (row & 7)) << 4)),
                  ws + (size_t)row * DD + q * 4);
        }
    }
    asm volatile("cp.async.commit_group;" ::: "memory");
}

__global__ __launch_bounds__(512, 1) void k_main(const float* __restrict__ x,
                                                 float* __restrict__ out, int N) {
    extern __shared__ char sm[];
    const int tid = threadIdx.x, wid = tid >> 5, lane = tid & 31;
    const int warp_m = wid & 7;        // 8 in M: 32 rows each
    const int warp_n = wid >> 3;       // 2 in N: w0 blocks 0-7, w1 blocks 8-13
    const int nt = blockIdx.x;
    const size_t row0 = (size_t)blockIdx.y * BM;
    const size_t NS = (size_t)N * 81;

    const int livecols = min(BNL, PCOLS - nt * BNL);          // 104 or 93
    const int liveblk  = (livecols + 7) >> 3;                 // 13 or 12
    const int njw = warp_n ? min(6, liveblk - 8) : 8;
    const int ngrp = warp_n ? 3 : 4;

    float* sBias = (float*)sm;
    for (int i = tid; i < BNP; i += 512) sBias[i] = g_bias[nt * BNP + i];

    uint32_t st[NSTAGE];
#pragma unroll
    for (int s = 0; s < NSTAGE; s++) st[s] = smem_u32(sm + 1024 + s * STAGE_SZ);

    const float* xrow0 = x + row0 * DD;
    const float* wrow0 = g_Wt + (size_t)nt * BNP * DD;

    int rA[2], rB[4];
    const int qbA = (lane >> 4) & 1;
    const int qbB = (lane >> 3) & 1;
#pragma unroll
    for (int mi = 0; mi < 2; mi++)
        rA[mi] = warp_m * 32 + mi * 16 + ((lane >> 3) & 1) * 8 + (lane & 7);
#pragma unroll
    for (int g = 0; g < 4; g++)
        rB[g] = warp_n * 64 + g * 16 + ((lane >> 4) & 1) * 8 + (lane & 7);

    float acc[2][8][4];
#pragma unroll
    for (int mi = 0; mi < 2; mi++)
#pragma unroll
        for (int nj = 0; nj < 8; nj++)
#pragma unroll
            for (int e = 0; e < 4; e++) acc[mi][nj][e] = 0.f;

    issue_stage(st[0], xrow0, wrow0, 0, tid);
    issue_stage(st[1], xrow0, wrow0, 1, tid);
    issue_stage(st[2], xrow0, wrow0, 2, tid);

    for (int c = 0; c < NCHUNK; c++) {
        uint32_t sb = st[c & 3];
        // complete chunk c: outstanding groups at top = {c .. min(31, c+2)}
        if (c <= NCHUNK - 3)      asm volatile("cp.async.wait_group 2;" ::: "memory");
        else if (c == NCHUNK - 2) asm volatile("cp.async.wait_group 1;" ::: "memory");
        else                      asm volatile("cp.async.wait_group 0;" ::: "memory");
        __syncthreads();   // also guarantees stage (c+3)&3 == (c-1)&3 fully consumed

        if (c + 3 < NCHUNK)
            issue_stage(st[(c + 3) & 3], xrow0, wrow0, c + 3, tid);

        const uint32_t Ab = sb, Bb = sb + A_BYTES;
#pragma unroll
        for (int kq2 = 0; kq2 < 4; kq2++) {
            uint32_t a[2][4];
#pragma unroll
            for (int mi = 0; mi < 2; mi++) {
                int r = rA[mi];
                ldsm4(a[mi], Ab + (uint32_t)(r * 128 + (((2 * kq2 + qbA) ^ (r & 7)) << 4)));
            }
            uint32_t b[4][4];
#pragma unroll
            for (int g = 0; g < 4; g++) {
                if (g < ngrp) {
                    int r = rB[g];
                    ldsm4(b[g], Bb + (uint32_t)(r * 128 + (((2 * kq2 + qbB) ^ (r & 7)) << 4)));
                }
            }
#pragma unroll
            for (int mi = 0; mi < 2; mi++)
#pragma unroll
                for (int nj = 0; nj < 8; nj++)
                    if (nj < njw)
                        mma8(acc[mi][nj], a[mi], b[nj >> 1][(nj & 1) * 2], b[nj >> 1][(nj & 1) * 2 + 1]);
        }
    }
    __syncthreads();

    // ---- epilogue: two 128-row halves through smem ----
    float* sC = (float*)(sm + 1024);
    float* outb = out + NS;
    const int tr = lane >> 2, tc2 = (lane & 3) * 2;
    const int jbase = nt * BNL;
#pragma unroll
    for (int half = 0; half < 2; half++) {
        __syncthreads();
        if ((warp_m >> 2) == half) {
            const int rb = (warp_m & 3) * 32;
#pragma unroll
            for (int mi = 0; mi < 2; mi++)
#pragma unroll
                for (int nj = 0; nj < 8; nj++)
                    if (nj < njw) {
                        int r = rb + mi * 16 + tr;
                        int cc = warp_n * 64 + nj * 8 + tc2;
                        *(float2*)&sC[r * LDC + cc]       = make_float2(acc[mi][nj][0], acc[mi][nj][1]);
                        *(float2*)&sC[(r + 8) * LDC + cc] = make_float2(acc[mi][nj][2], acc[mi][nj][3]);
                    }
        }
        __syncthreads();
        for (int e = tid; e < 128 * livecols; e += 512) {
            int row = e / livecols, n = e % livecols;
            int j = jbase + n;
            float v = sC[row * LDC + n] + sBias[n];
            size_t gr = row0 + half * 128 + row;
            if (j < 81) out[gr * 81 + j] = v;
            else        outb[gr * 324 + (j - 81)] = v;
        }
    }
}

// ---------------- launch ----------------
extern "C" void kernel_launch(void* const* d_in, const int* in_sizes, int n_in,
                              void* d_out, int out_size) {
    const float* x    = (const float*)d_in[0];
    const float* Wcls = (const float*)d_in[1];
    const float* bcls = (const float*)d_in[2];
    const float* Wsem = (const float*)d_in[3];
    const float* bsem = (const float*)d_in[4];
    const float* Wbb  = (const float*)d_in[5];
    const float* bbb  = (const float*)d_in[6];
    const float* semm = (const float*)d_in[7];
    float* out = (float*)d_out;
    int N = in_sizes[0] / DD;

    cudaFuncSetAttribute(k_main, cudaFuncAttributeMaxDynamicSharedMemorySize, SMEM_DYN);

    k_prep<<<NTILE * BNP, 256>>>(Wcls, bcls, Wsem, bsem, Wbb, bbb, semm);
    dim3 grid(NTILE, N / BM);
    k_main<<<grid, 512, SMEM_DYN>>>(x, out, N);
}

// round 9
// speedup vs baseline: 4.5831x; 1.0517x over previous
#include <cuda_runtime.h>
#include <cstdint>
#include <cstddef>

// ---------------- problem constants ----------------
#define DD     1024
#define PCOLS  405       // 1 + 80 + 324
#define NTILE  4
#define BNL    104       // live cols per tile
#define BNP    112       // padded rows per tile (14 n8 blocks)
#define NF     300
#define BM     128
#define BK     32
#define NCHUNK (DD / BK)
#define NSTAGE 3

#define A_BYTES  (BM * 128)              // 16384
#define B_BYTES  (BNP * 128)             // 14336
#define STAGE_SZ (A_BYTES + B_BYTES)     // 30720
#define SMEM_DYN (1024 + NSTAGE * STAGE_SZ)  // 93184 -> 2 CTAs/SM
#define LDC      120

// ---------------- device scratch ----------------
__device__ float g_Wt[(size_t)NTILE * BNP * DD];
__device__ float g_bias[NTILE * BNP];

__device__ __forceinline__ float to_tf32(float f) {
    float r; asm("cvt.rna.tf32.f32 %0, %1;" : "=f"(r) : "f"(f)); return r;
}
__device__ __forceinline__ uint32_t smem_u32(const void* p) {
    uint32_t a;
    asm("{ .reg .u64 t; cvta.to.shared.u64 t, %1; cvt.u32.u64 %0, t; }" : "=r"(a) : "l"(p));
    return a;
}
__device__ __forceinline__ void cpa16(uint32_t dst, const void* src) {
    asm volatile("cp.async.cg.shared.global [%0], [%1], 16;" :: "r"(dst), "l"(src));
}
__device__ __forceinline__ void ldsm4(uint32_t r[4], uint32_t addr) {
    asm volatile("ldmatrix.sync.aligned.m8n8.x4.shared.b16 {%0,%1,%2,%3}, [%4];"
        : "=r"(r[0]), "=r"(r[1]), "=r"(r[2]), "=r"(r[3]) : "r"(addr));
}
__device__ __forceinline__ void mma8(float d[4], const uint32_t a[4], uint32_t b0, uint32_t b1) {
    asm volatile(
        "mma.sync.aligned.m16n8k8.row.col.f32.tf32.tf32.f32 "
        "{%0,%1,%2,%3}, {%4,%5,%6,%7}, {%8,%9}, {%0,%1,%2,%3};"
        : "+f"(d[0]), "+f"(d[1]), "+f"(d[2]), "+f"(d[3])
        : "r"(a[0]), "r"(a[1]), "r"(a[2]), "r"(a[3]), "r"(b0), "r"(b1));
}

// ---------------- prep: fused W rows (tf32-pre-rounded) + bias ----------------
__global__ void k_prep(const float* __restrict__ Wcls, const float* __restrict__ bcls,
                       const float* __restrict__ Wsem, const float* __restrict__ bsem,
                       const float* __restrict__ Wbb,  const float* __restrict__ bbb,
                       const float* __restrict__ semm) {
    __shared__ float srow[NF];
    __shared__ float ws[8];
    const int b = blockIdx.x, t = threadIdx.x;
    const int tile = b / BNP, r = b % BNP;
    const int j = tile * BNL + r;
    float* wo = g_Wt + (size_t)b * DD;

    if (r >= BNL || j >= PCOLS) {
        for (int d = t; d < DD; d += 256) wo[d] = 0.f;
        if (t == 0) g_bias[b] = 0.f;
        return;
    }
    if (j == 0) {
        for (int d = t; d < DD; d += 256) wo[d] = to_tf32(Wcls[d]);
        if (t == 0) g_bias[b] = bcls[0];
    } else if (j <= 80) {
        const int c = j - 1;
        float ss = 0.f;
        for (int f = t; f < NF; f += 256) { float v = semm[c * NF + f]; ss += v * v; }
        for (int o = 16; o; o >>= 1) ss += __shfl_xor_sync(0xffffffffu, ss, o);
        if ((t & 31) == 0) ws[t >> 5] = ss;
        __syncthreads();
        float tot = 0.f;
#pragma unroll
        for (int i = 0; i < 8; i++) tot += ws[i];
        const float scale = 8.0f * rsqrtf(tot);
        for (int f = t; f < NF; f += 256) srow[f] = semm[c * NF + f] * scale;
        __syncthreads();
        float a0 = 0.f, a1 = 0.f, a2 = 0.f, a3 = 0.f;
#pragma unroll 6
        for (int f = 0; f < NF; f++) {
            float s = srow[f];
            const float* wp = Wsem + (size_t)f * DD + t;
            a0 += s * wp[0]; a1 += s * wp[256]; a2 += s * wp[512]; a3 += s * wp[768];
        }
        wo[t] = to_tf32(a0); wo[t + 256] = to_tf32(a1);
        wo[t + 512] = to_tf32(a2); wo[t + 768] = to_tf32(a3);
        if (t == 0) {
            float bb = 0.f;
            for (int f = 0; f < NF; f++) bb += srow[f] * bsem[f];
            g_bias[b] = bb;
        }
    } else {
        const int i = j - 81;
        for (int d = t; d < DD; d += 256) wo[d] = to_tf32(Wbb[(size_t)i * DD + d]);
        if (t == 0) g_bias[b] = bbb[i];
    }
}

// ---------------- main GEMM: BM=128, 256 thr, occ=2, 3-stage cp.async ----------------
__device__ __forceinline__ void issue_stage(uint32_t sbase, const float* __restrict__ xrow0,
                                            const float* __restrict__ wrow0, int c, int tid) {
    const float* xs = xrow0 + c * BK;
    const float* ws = wrow0 + c * BK;
#pragma unroll
    for (int i = 0; i < 4; i++) {               // A: 128 rows x 8 quads = 1024
        int seg = tid + i * 256;
        int row = seg >> 3, q = seg & 7;
        cpa16(sbase + (uint32_t)(row * 128 + ((q ^ (row & 7)) << 4)),
              xs + (size_t)row * DD + q * 4);
    }
#pragma unroll
    for (int i = 0; i < 4; i++) {               // B: 112 rows x 8 quads = 896
        int seg = tid + i * 256;
        if (seg < BNP * 8) {
            int row = seg >> 3, q = seg & 7;
            cpa16(sbase + (uint32_t)(A_BYTES + row * 128 + ((q ^ (row & 7)) << 4)),
                  ws + (size_t)row * DD + q * 4);
        }
    }
    asm volatile("cp.async.commit_group;" ::: "memory");
}

__global__ __launch_bounds__(256, 2) void k_main(const float* __restrict__ x,
                                                 float* __restrict__ out, int N) {
    extern __shared__ char sm[];
    const int tid = threadIdx.x, wid = tid >> 5, lane = tid & 31;
    const int warp_m = wid & 3;        // 4 in M: 32 rows each
    const int warp_n = wid >> 2;       // 2 in N: w0 blocks 0-7, w1 blocks 8-13
    const int nt = blockIdx.x;
    const size_t row0 = (size_t)blockIdx.y * BM;
    const size_t NS = (size_t)N * 81;

    const int livecols = min(BNL, PCOLS - nt * BNL);          // 104 or 93
    const int liveblk  = (livecols + 7) >> 3;                 // 13 or 12
    const int njw = warp_n ? min(6, liveblk - 8) : 8;         // 8 | 5/4
    const int ngrp = warp_n ? 3 : 4;

    float* sBias = (float*)sm;
    for (int i = tid; i < BNP; i += 256) sBias[i] = g_bias[nt * BNP + i];

    uint32_t st[NSTAGE];
#pragma unroll
    for (int s = 0; s < NSTAGE; s++) st[s] = smem_u32(sm + 1024 + s * STAGE_SZ);

    const float* xrow0 = x + row0 * DD;
    const float* wrow0 = g_Wt + (size_t)nt * BNP * DD;

    int rA[2], rB[4];
    const int qbA = (lane >> 4) & 1;
    const int qbB = (lane >> 3) & 1;
#pragma unroll
    for (int mi = 0; mi < 2; mi++)
        rA[mi] = warp_m * 32 + mi * 16 + ((lane >> 3) & 1) * 8 + (lane & 7);
#pragma unroll
    for (int g = 0; g < 4; g++)
        rB[g] = warp_n * 64 + g * 16 + ((lane >> 4) & 1) * 8 + (lane & 7);

    float acc[2][8][4];
#pragma unroll
    for (int mi = 0; mi < 2; mi++)
#pragma unroll
        for (int nj = 0; nj < 8; nj++)
#pragma unroll
            for (int e = 0; e < 4; e++) acc[mi][nj][e] = 0.f;

    issue_stage(st[0], xrow0, wrow0, 0, tid);
    issue_stage(st[1], xrow0, wrow0, 1, tid);

    for (int c = 0; c < NCHUNK; c++) {
        uint32_t sb = st[c % NSTAGE];
        if (c == NCHUNK - 1) asm volatile("cp.async.wait_group 0;" ::: "memory");
        else                 asm volatile("cp.async.wait_group 1;" ::: "memory");
        __syncthreads();     // stage c ready; stage (c+2)%3 drained (consumed pre-barrier at c-1)
        if (c + 2 < NCHUNK)
            issue_stage(st[(c + 2) % NSTAGE], xrow0, wrow0, c + 2, tid);

        const uint32_t Ab = sb, Bb = sb + A_BYTES;
#pragma unroll
        for (int kq2 = 0; kq2 < 4; kq2++) {
            uint32_t a[2][4];
#pragma unroll
            for (int mi = 0; mi < 2; mi++) {
                int r = rA[mi];
                ldsm4(a[mi], Ab + (uint32_t)(r * 128 + (((2 * kq2 + qbA) ^ (r & 7)) << 4)));
            }
            uint32_t b[4][4];
#pragma unroll
            for (int g = 0; g < 4; g++) {
                if (g < ngrp) {
                    int r = rB[g];
                    ldsm4(b[g], Bb + (uint32_t)(r * 128 + (((2 * kq2 + qbB) ^ (r & 7)) << 4)));
                }
            }
#pragma unroll
            for (int mi = 0; mi < 2; mi++)
#pragma unroll
                for (int nj = 0; nj < 8; nj++)
                    if (nj < njw)
                        mma8(acc[mi][nj], a[mi], b[nj >> 1][(nj & 1) * 2], b[nj >> 1][(nj & 1) * 2 + 1]);
        }
    }
    __syncthreads();

    // ---- epilogue: frags -> smem -> biased scatter ----
    float* sC = (float*)(sm + 1024);
    const int tr = lane >> 2, tc2 = (lane & 3) * 2;
#pragma unroll
    for (int mi = 0; mi < 2; mi++)
#pragma unroll
        for (int nj = 0; nj < 8; nj++)
            if (nj < njw) {
                int r = warp_m * 32 + mi * 16 + tr;
                int cc = warp_n * 64 + nj * 8 + tc2;
                *(float2*)&sC[r * LDC + cc]       = make_float2(acc[mi][nj][0], acc[mi][nj][1]);
                *(float2*)&sC[(r + 8) * LDC + cc] = make_float2(acc[mi][nj][2], acc[mi][nj][3]);
            }
    __syncthreads();

    float* outb = out + NS;
    const int jbase = nt * BNL;
    for (int e = tid; e < BM * livecols; e += 256) {
        int row = e / livecols, n = e % livecols;
        int j = jbase + n;
        float v = sC[row * LDC + n] + sBias[n];
        size_t gr = row0 + row;
        if (j < 81) out[gr * 81 + j] = v;
        else        outb[gr * 324 + (j - 81)] = v;
    }
}

// ---------------- launch ----------------
extern "C" void kernel_launch(void* const* d_in, const int* in_sizes, int n_in,
                              void* d_out, int out_size) {
    const float* x    = (const float*)d_in[0];
    const float* Wcls = (const float*)d_in[1];
    const float* bcls = (const float*)d_in[2];
    const float* Wsem = (const float*)d_in[3];
    const float* bsem = (const float*)d_in[4];
    const float* Wbb  = (const float*)d_in[5];
    const float* bbb  = (const float*)d_in[6];
    const float* semm = (const float*)d_in[7];
    float* out = (float*)d_out;
    int N = in_sizes[0] / DD;

    cudaFuncSetAttribute(k_main, cudaFuncAttributeMaxDynamicSharedMemorySize, SMEM_DYN);

    k_prep<<<NTILE * BNP, 256>>>(Wcls, bcls, Wsem, bsem, Wbb, bbb, semm);
    dim3 grid(NTILE, N / BM);
    k_main<<<grid, 256, SMEM_DYN>>>(x, out, N);
}

// round 10
// speedup vs baseline: 5.3506x; 1.1674x over previous
#include <cuda_runtime.h>
#include <cstdint>
#include <cstddef>

// ---------------- problem constants ----------------
#define DD     1024
#define PCOLS  405       // 1 + 80 + 324
#define NTILE  4
#define BNL    104       // live cols per tile
#define BNP    112       // padded rows per tile
#define NF     300
#define BM     128
#define BK     32
#define NCHUNK (DD / BK)
#define NSTAGE 3

#define A_BYTES  (BM * 128)              // 16384
#define B_BYTES  (BNP * 128)             // 14336
#define STAGE_SZ (A_BYTES + B_BYTES)     // 30720
#define SMEM_DYN (1024 + NSTAGE * STAGE_SZ)  // 93184 -> 2 CTAs/SM
#define LDC      120

// ---------------- device scratch ----------------
__device__ float g_Wt[(size_t)NTILE * BNP * DD];
__device__ float g_bias[NTILE * BNP];

__device__ __forceinline__ float to_tf32(float f) {
    float r; asm("cvt.rna.tf32.f32 %0, %1;" : "=f"(r) : "f"(f)); return r;
}
__device__ __forceinline__ uint32_t smem_u32(const void* p) {
    uint32_t a;
    asm("{ .reg .u64 t; cvta.to.shared.u64 t, %1; cvt.u32.u64 %0, t; }" : "=r"(a) : "l"(p));
    return a;
}
__device__ __forceinline__ void cpa16(uint32_t dst, const void* src) {
    asm volatile("cp.async.cg.shared.global [%0], [%1], 16;" :: "r"(dst), "l"(src));
}
__device__ __forceinline__ void ldsm4(uint32_t r[4], uint32_t addr) {
    asm volatile("ldmatrix.sync.aligned.m8n8.x4.shared.b16 {%0,%1,%2,%3}, [%4];"
        : "=r"(r[0]), "=r"(r[1]), "=r"(r[2]), "=r"(r[3]) : "r"(addr));
}
__device__ __forceinline__ void mma8(float d[4], const uint32_t a[4], uint32_t b0, uint32_t b1) {
    asm volatile(
        "mma.sync.aligned.m16n8k8.row.col.f32.tf32.tf32.f32 "
        "{%0,%1,%2,%3}, {%4,%5,%6,%7}, {%8,%9}, {%0,%1,%2,%3};"
        : "+f"(d[0]), "+f"(d[1]), "+f"(d[2]), "+f"(d[3])
        : "r"(a[0]), "r"(a[1]), "r"(a[2]), "r"(a[3]), "r"(b0), "r"(b1));
}

// ---------------- prep: fused W rows (tf32-pre-rounded) + bias ----------------
__global__ void k_prep(const float* __restrict__ Wcls, const float* __restrict__ bcls,
                       const float* __restrict__ Wsem, const float* __restrict__ bsem,
                       const float* __restrict__ Wbb,  const float* __restrict__ bbb,
                       const float* __restrict__ semm) {
    __shared__ float srow[NF];
    __shared__ float ws[8];
    const int b = blockIdx.x, t = threadIdx.x;
    const int tile = b / BNP, r = b % BNP;
    const int j = tile * BNL + r;
    float* wo = g_Wt + (size_t)b * DD;

    if (r >= BNL || j >= PCOLS) {
        for (int d = t; d < DD; d += 256) wo[d] = 0.f;
        if (t == 0) g_bias[b] = 0.f;
        return;
    }
    if (j == 0) {
        for (int d = t; d < DD; d += 256) wo[d] = to_tf32(Wcls[d]);
        if (t == 0) g_bias[b] = bcls[0];
    } else if (j <= 80) {
        const int c = j - 1;
        float ss = 0.f;
        for (int f = t; f < NF; f += 256) { float v = semm[c * NF + f]; ss += v * v; }
        for (int o = 16; o; o >>= 1) ss += __shfl_xor_sync(0xffffffffu, ss, o);
        if ((t & 31) == 0) ws[t >> 5] = ss;
        __syncthreads();
        float tot = 0.f;
#pragma unroll
        for (int i = 0; i < 8; i++) tot += ws[i];
        const float scale = 8.0f * rsqrtf(tot);
        for (int f = t; f < NF; f += 256) srow[f] = semm[c * NF + f] * scale;
        __syncthreads();
        float a0 = 0.f, a1 = 0.f, a2 = 0.f, a3 = 0.f;
#pragma unroll 6
        for (int f = 0; f < NF; f++) {
            float s = srow[f];
            const float* wp = Wsem + (size_t)f * DD + t;
            a0 += s * wp[0]; a1 += s * wp[256]; a2 += s * wp[512]; a3 += s * wp[768];
        }
        wo[t] = to_tf32(a0); wo[t + 256] = to_tf32(a1);
        wo[t + 512] = to_tf32(a2); wo[t + 768] = to_tf32(a3);
        // warp-parallel bias dot (was serial on t==0: the hidden 60us)
        if (t < 32) {
            float bb = 0.f;
            for (int f = t; f < NF; f += 32) bb += srow[f] * bsem[f];
            for (int o = 16; o; o >>= 1) bb += __shfl_xor_sync(0xffffffffu, bb, o);
            if (t == 0) g_bias[b] = bb;
        }
    } else {
        const int i = j - 81;
        for (int d = t; d < DD; d += 256) wo[d] = to_tf32(Wbb[(size_t)i * DD + d]);
        if (t == 0) g_bias[b] = bbb[i];
    }
}

// ---------------- main GEMM: BM=128, 256 thr, occ=2, 3-stage, templated split ----------------
__device__ __forceinline__ void issue_stage(uint32_t sbase, const float* __restrict__ xrow0,
                                            const float* __restrict__ wrow0, int c, int tid) {
    const float* xs = xrow0 + c * BK;
    const float* ws = wrow0 + c * BK;
#pragma unroll
    for (int i = 0; i < 4; i++) {               // A: 128 rows x 8 quads
        int seg = tid + i * 256;
        int row = seg >> 3, q = seg & 7;
        cpa16(sbase + (uint32_t)(row * 128 + ((q ^ (row & 7)) << 4)),
              xs + (size_t)row * DD + q * 4);
    }
#pragma unroll
    for (int i = 0; i < 4; i++) {               // B: 112 rows x 8 quads
        int seg = tid + i * 256;
        if (seg < BNP * 8) {
            int row = seg >> 3, q = seg & 7;
            cpa16(sbase + (uint32_t)(A_BYTES + row * 128 + ((q ^ (row & 7)) << 4)),
                  ws + (size_t)row * DD + q * 4);
        }
    }
    asm volatile("cp.async.commit_group;" ::: "memory");
}

// NJ0/NJ1: n8 blocks for warp_n 0/1. G0: ldsm x4 groups for w0. NB1: w1 row base.
template <int NJ0, int NJ1, int G0, int NB1>
__device__ __forceinline__ void gemm_body(char* sm, const float* __restrict__ x,
                                          float* __restrict__ out, int N,
                                          int nt, int livecols) {
    const int tid = threadIdx.x, wid = tid >> 5, lane = tid & 31;
    const int warp_m = wid & 3;
    const int warp_n = wid >> 2;
    const size_t row0 = (size_t)blockIdx.y * BM;
    const size_t NS = (size_t)N * 81;
    const int NJ = warp_n ? NJ1 : NJ0;
    const int NG = warp_n ? ((NJ1 + 1) >> 1) : G0;
    const int colbase = warp_n ? NB1 : 0;

    float* sBias = (float*)sm;
    for (int i = tid; i < BNP; i += 256) sBias[i] = g_bias[nt * BNP + i];

    uint32_t st[NSTAGE];
#pragma unroll
    for (int s = 0; s < NSTAGE; s++) st[s] = smem_u32(sm + 1024 + s * STAGE_SZ);

    const float* xrow0 = x + row0 * DD;
    const float* wrow0 = g_Wt + (size_t)nt * BNP * DD;

    int rA[2], rB[4];
    const int qbA = (lane >> 4) & 1;
    const int qbB = (lane >> 3) & 1;
#pragma unroll
    for (int mi = 0; mi < 2; mi++)
        rA[mi] = warp_m * 32 + mi * 16 + ((lane >> 3) & 1) * 8 + (lane & 7);
#pragma unroll
    for (int g = 0; g < 4; g++)
        rB[g] = colbase + g * 16 + ((lane >> 4) & 1) * 8 + (lane & 7);

    float acc[2][NJ0][4];   // NJ0 >= NJ1
#pragma unroll
    for (int mi = 0; mi < 2; mi++)
#pragma unroll
        for (int nj = 0; nj < NJ0; nj++)
#pragma unroll
            for (int e = 0; e < 4; e++) acc[mi][nj][e] = 0.f;

    issue_stage(st[0], xrow0, wrow0, 0, tid);
    issue_stage(st[1], xrow0, wrow0, 1, tid);

    for (int c = 0; c < NCHUNK; c++) {
        uint32_t sb = st[c % NSTAGE];
        if (c == NCHUNK - 1) asm volatile("cp.async.wait_group 0;" ::: "memory");
        else                 asm volatile("cp.async.wait_group 1;" ::: "memory");
        __syncthreads();
        if (c + 2 < NCHUNK)
            issue_stage(st[(c + 2) % NSTAGE], xrow0, wrow0, c + 2, tid);

        const uint32_t Ab = sb, Bb = sb + A_BYTES;
#pragma unroll
        for (int kq2 = 0; kq2 < 4; kq2++) {
            uint32_t a[2][4];
#pragma unroll
            for (int mi = 0; mi < 2; mi++) {
                int r = rA[mi];
                ldsm4(a[mi], Ab + (uint32_t)(r * 128 + (((2 * kq2 + qbA) ^ (r & 7)) << 4)));
            }
            uint32_t b[4][4];
#pragma unroll
            for (int g = 0; g < 4; g++) {
                if (g < NG) {
                    int r = rB[g];
                    ldsm4(b[g], Bb + (uint32_t)(r * 128 + (((2 * kq2 + qbB) ^ (r & 7)) << 4)));
                }
            }
            if (warp_n == 0) {
#pragma unroll
                for (int mi = 0; mi < 2; mi++)
#pragma unroll
                    for (int nj = 0; nj < NJ0; nj++)
                        mma8(acc[mi][nj], a[mi], b[nj >> 1][(nj & 1) * 2], b[nj >> 1][(nj & 1) * 2 + 1]);
            } else {
#pragma unroll
                for (int mi = 0; mi < 2; mi++)
#pragma unroll
                    for (int nj = 0; nj < NJ1; nj++)
                        mma8(acc[mi][nj], a[mi], b[nj >> 1][(nj & 1) * 2], b[nj >> 1][(nj & 1) * 2 + 1]);
            }
        }
    }
    __syncthreads();

    // ---- epilogue ----
    float* sC = (float*)(sm + 1024);
    const int tr = lane >> 2, tc2 = (lane & 3) * 2;
#pragma unroll
    for (int mi = 0; mi < 2; mi++)
#pragma unroll
        for (int nj = 0; nj < NJ0; nj++)
            if (nj < NJ) {
                int r = warp_m * 32 + mi * 16 + tr;
                int cc = colbase + nj * 8 + tc2;
                *(float2*)&sC[r * LDC + cc]       = make_float2(acc[mi][nj][0], acc[mi][nj][1]);
                *(float2*)&sC[(r + 8) * LDC + cc] = make_float2(acc[mi][nj][2], acc[mi][nj][3]);
            }
    __syncthreads();

    float* outb = out + NS;
    const int jbase = nt * BNL;
    for (int e = tid; e < BM * livecols; e += 256) {
        int row = e / livecols, n = e % livecols;
        int j = jbase + n;
        float v = sC[row * LDC + n] + sBias[n];
        size_t gr = row0 + row;
        if (j < 81) out[gr * 81 + j] = v;
        else        outb[gr * 324 + (j - 81)] = v;
    }
}

__global__ __launch_bounds__(256, 2) void k_main(const float* __restrict__ x,
                                                 float* __restrict__ out, int N) {
    extern __shared__ char sm[];
    const int nt = blockIdx.x;
    if (nt < 3) gemm_body<7, 6, 4, 56>(sm, x, out, N, nt, BNL);       // 13 blocks: 7/6
    else        gemm_body<6, 6, 3, 48>(sm, x, out, N, nt, PCOLS - 3 * BNL);  // 12 blocks: 6/6
}

// ---------------- launch ----------------
extern "C" void kernel_launch(void* const* d_in, const int* in_sizes, int n_in,
                              void* d_out, int out_size) {
    const float* x    = (const float*)d_in[0];
    const float* Wcls = (const float*)d_in[1];
    const float* bcls = (const float*)d_in[2];
    const float* Wsem = (const float*)d_in[3];
    const float* bsem = (const float*)d_in[4];
    const float* Wbb  = (const float*)d_in[5];
    const float* bbb  = (const float*)d_in[6];
    const float* semm = (const float*)d_in[7];
    float* out = (float*)d_out;
    int N = in_sizes[0] / DD;

    cudaFuncSetAttribute(k_main, cudaFuncAttributeMaxDynamicSharedMemorySize, SMEM_DYN);

    k_prep<<<NTILE * BNP, 256>>>(Wcls, bcls, Wsem, bsem, Wbb, bbb, semm);
    dim3 grid(NTILE, N / BM);
    k_main<<<grid, 256, SMEM_DYN>>>(x, out, N);
}

// round 11
// speedup vs baseline: 5.6157x; 1.0495x over previous
#include <cuda_runtime.h>
#include <cuda_fp16.h>
#include <cstdint>
#include <cstddef>

// ---------------- problem constants ----------------
#define DD     1024
#define PCOLS  405       // 1 + 80 + 324
#define NTILE  4
#define BNL    104       // live cols per tile
#define BNP    112       // padded rows per tile
#define NF     300
#define BM     128
#define BK     64        // fp16: 64 halves = 128B rows -> SW128 swizzle
#define NCHUNK (DD / BK) // 16
#define NSTAGE 3

#define A_BYTES  (BM * 128)              // 16384
#define B_BYTES  (BNP * 128)             // 14336
#define STAGE_SZ (A_BYTES + B_BYTES)     // 30720
#define SMEM_DYN (1024 + NSTAGE * STAGE_SZ)  // 93184 -> 2 CTAs/SM
#define LDC      120

// ---------------- device scratch ----------------
__device__ __half g_Wh[(size_t)NTILE * BNP * DD];
__device__ float  g_bias[NTILE * BNP];

// ---------------- helpers ----------------
__device__ __forceinline__ uint32_t smem_u32(const void* p) {
    uint32_t a;
    asm("{ .reg .u64 t; cvta.to.shared.u64 t, %1; cvt.u32.u64 %0, t; }" : "=r"(a) : "l"(p));
    return a;
}
__device__ __forceinline__ void cpa16(uint32_t dst, const void* src) {
    asm volatile("cp.async.cg.shared.global [%0], [%1], 16;" :: "r"(dst), "l"(src));
}
__device__ __forceinline__ void ldsm4(uint32_t r[4], uint32_t addr) {
    asm volatile("ldmatrix.sync.aligned.m8n8.x4.shared.b16 {%0,%1,%2,%3}, [%4];"
        : "=r"(r[0]), "=r"(r[1]), "=r"(r[2]), "=r"(r[3]) : "r"(addr));
}
__device__ __forceinline__ void mma16(float d[4], const uint32_t a[4], uint32_t b0, uint32_t b1) {
    asm volatile(
        "mma.sync.aligned.m16n8k16.row.col.f32.f16.f16.f32 "
        "{%0,%1,%2,%3}, {%4,%5,%6,%7}, {%8,%9}, {%0,%1,%2,%3};"
        : "+f"(d[0]), "+f"(d[1]), "+f"(d[2]), "+f"(d[3])
        : "r"(a[0]), "r"(a[1]), "r"(a[2]), "r"(a[3]), "r"(b0), "r"(b1));
}
__device__ __forceinline__ void sts16(uint32_t addr, uint4 v) {
    asm volatile("st.shared.v4.b32 [%0], {%1,%2,%3,%4};"
        :: "r"(addr), "r"(v.x), "r"(v.y), "r"(v.z), "r"(v.w));
}
__device__ __forceinline__ uint4 pack8(float4 a, float4 b) {
    __half2 h0 = __floats2half2_rn(a.x, a.y);
    __half2 h1 = __floats2half2_rn(a.z, a.w);
    __half2 h2 = __floats2half2_rn(b.x, b.y);
    __half2 h3 = __floats2half2_rn(b.z, b.w);
    uint4 u;
    u.x = *reinterpret_cast<uint32_t*>(&h0);
    u.y = *reinterpret_cast<uint32_t*>(&h1);
    u.z = *reinterpret_cast<uint32_t*>(&h2);
    u.w = *reinterpret_cast<uint32_t*>(&h3);
    return u;
}

// ---------------- k_fold: W_eff[80,1024] = (8*norm(semm)) @ Wsem, tiled, fp16 out ----
__global__ void k_fold(const float* __restrict__ Wsem, const float* __restrict__ bsem,
                       const float* __restrict__ semm) {
    __shared__ float ssm[16 * NF];
    __shared__ float sscale[16];
    const int rg = blockIdx.y;        // 0..4 (16 rows each)
    const int cg = blockIdx.x;        // 0..3 (256 cols each)
    const int t = threadIdx.x, wid = t >> 5, lane = t & 31;
    const int r0 = rg * 16, c0 = cg * 256;

    // norms: warp w -> rows 2w, 2w+1
#pragma unroll
    for (int rr = 0; rr < 2; rr++) {
        int ri = wid * 2 + rr;
        const float* src = semm + (size_t)(r0 + ri) * NF;
        float ss = 0.f;
        for (int f = lane; f < NF; f += 32) { float v = src[f]; ss += v * v; }
        for (int o = 16; o; o >>= 1) ss += __shfl_xor_sync(~0u, ss, o);
        if (lane == 0) sscale[ri] = 8.0f * rsqrtf(ss);
    }
    __syncthreads();
    for (int idx = t; idx < 16 * NF; idx += 256) {
        int ri = idx / NF, f = idx - ri * NF;
        ssm[ri * NF + f] = semm[(size_t)(r0 + ri) * NF + f] * sscale[ri];
    }
    __syncthreads();

    float acc[16];
#pragma unroll
    for (int i = 0; i < 16; i++) acc[i] = 0.f;
    const float* wp = Wsem + c0 + t;
#pragma unroll 8
    for (int f = 0; f < NF; f++) {
        float w = wp[(size_t)f * DD];
#pragma unroll
        for (int ri = 0; ri < 16; ri++) acc[ri] += ssm[ri * NF + f] * w;
    }
#pragma unroll
    for (int ri = 0; ri < 16; ri++) {
        int p = 1 + r0 + ri;     // padded row: j=1..80 -> tile0 row j
        g_Wh[(size_t)p * DD + c0 + t] = __float2half_rn(acc[ri]);
    }
    if (cg == 0) {
#pragma unroll
        for (int rr = 0; rr < 2; rr++) {
            int ri = wid * 2 + rr;
            float bb = 0.f;
            for (int f = lane; f < NF; f += 32) bb += ssm[ri * NF + f] * bsem[f];
            for (int o = 16; o; o >>= 1) bb += __shfl_xor_sync(~0u, bb, o);
            if (lane == 0) g_bias[1 + r0 + ri] = bb;
        }
    }
}

// ---------------- k_copy: cls/bbox rows -> fp16, bias, padding ----------------
__global__ void k_copy(const float* __restrict__ Wcls, const float* __restrict__ bcls,
                       const float* __restrict__ Wbb,  const float* __restrict__ bbb) {
    const int p = blockIdx.x, t = threadIdx.x;
    const int tile = p / BNP, r = p - tile * BNP;
    const int j = tile * BNL + r;
    __half* wo = g_Wh + (size_t)p * DD;
    if (r >= BNL || j >= PCOLS) {
        for (int d = t; d < DD; d += 256) wo[d] = __float2half_rn(0.f);
        if (t == 0) g_bias[p] = 0.f;
    } else if (j == 0) {
        for (int d = t; d < DD; d += 256) wo[d] = __float2half_rn(Wcls[d]);
        if (t == 0) g_bias[p] = bcls[0];
    } else if (j <= 80) {
        // sem rows written by k_fold
    } else {
        const int i = j - 81;
        for (int d = t; d < DD; d += 256) wo[d] = __float2half_rn(Wbb[(size_t)i * DD + d]);
        if (t == 0) g_bias[p] = bbb[i];
    }
}

// ---------------- main GEMM: fp16 m16n8k16, fused A conversion ----------------
__device__ __forceinline__ void issueB(uint32_t sbase, const __half* __restrict__ wrow0,
                                       int c, int tid) {
    const __half* ws = wrow0 + c * BK;
#pragma unroll
    for (int i = 0; i < 4; i++) {
        int seg = tid + i * 256;
        if (seg < BNP * 8) {
            int row = seg >> 3, q = seg & 7;
            cpa16(sbase + (uint32_t)(A_BYTES + row * 128 + ((q ^ (row & 7)) << 4)),
                  ws + (size_t)row * DD + q * 8);
        }
    }
    asm volatile("cp.async.commit_group;" ::: "memory");
}

template <int NJ0, int NJ1, int NB1, int LIVE>
__device__ __forceinline__ void gemm_body(char* sm, const float* __restrict__ x,
                                          float* __restrict__ out, int N, int nt) {
    const int tid = threadIdx.x, wid = tid >> 5, lane = tid & 31;
    const int warp_m = wid & 3;
    const int warp_n = wid >> 2;
    const size_t row0 = (size_t)blockIdx.y * BM;
    const size_t NS = (size_t)N * 81;
    const int NJ = warp_n ? NJ1 : NJ0;
    const int NPAIR = warp_n ? ((NJ1 + 1) >> 1) : ((NJ0 + 1) >> 1);
    const int colbase = warp_n ? NB1 : 0;

    float* sBias = (float*)sm;
    for (int i = tid; i < BNP; i += 256) sBias[i] = g_bias[nt * BNP + i];

    uint32_t st[NSTAGE];
#pragma unroll
    for (int s = 0; s < NSTAGE; s++) st[s] = smem_u32(sm + 1024 + s * STAGE_SZ);

    const float*  xrow0 = x + row0 * DD;
    const __half* wrow0 = g_Wh + (size_t)nt * BNP * DD;

    // per-thread A staging offsets (4 quads)
    uint32_t aoff[4]; uint32_t goff[4];
#pragma unroll
    for (int i = 0; i < 4; i++) {
        int seg = tid + i * 256;
        int row = seg >> 3, q = seg & 7;
        aoff[i] = (uint32_t)(row * 128 + ((q ^ (row & 7)) << 4));
        goff[i] = (uint32_t)(row * DD + q * 8);
    }

    // ldsm address components (row&7 invariant under +16)
    const int rAr = warp_m * 32 + ((lane >> 3) & 1) * 8 + (lane & 7);
    const int qbA = lane >> 4;
    const uint32_t abase0 = (uint32_t)rAr * 128, abase1 = (uint32_t)(rAr + 16) * 128;
    const uint32_t axor = (uint32_t)(rAr & 7);
    const int rBr = colbase + ((lane >> 4)) * 8 + (lane & 7);
    const int qbB = (lane >> 3) & 1;
    uint32_t bbase[4];
#pragma unroll
    for (int g = 0; g < 4; g++) bbase[g] = (uint32_t)(rBr + g * 16) * 128;
    const uint32_t bxor = (uint32_t)(rBr & 7);

    float acc[2][NJ0][4];
#pragma unroll
    for (int mi = 0; mi < 2; mi++)
#pragma unroll
        for (int nj = 0; nj < NJ0; nj++)
#pragma unroll
            for (int e = 0; e < 4; e++) acc[mi][nj][e] = 0.f;

    uint4 buf[4];
    // ---- prologue: chunk 0 direct, chunk 1 into buf ----
    {
#pragma unroll
        for (int i = 0; i < 4; i++) {
            float4 ra = *(const float4*)(xrow0 + goff[i]);
            float4 rb = *(const float4*)(xrow0 + goff[i] + 4);
            sts16(st[0] + aoff[i], pack8(ra, rb));
        }
        issueB(st[0], wrow0, 0, tid);
#pragma unroll
        for (int i = 0; i < 4; i++) {
            float4 ra = *(const float4*)(xrow0 + BK + goff[i]);
            float4 rb = *(const float4*)(xrow0 + BK + goff[i] + 4);
            buf[i] = pack8(ra, rb);
        }
        issueB(st[1], wrow0, 1, tid);
    }

    for (int c = 0; c < NCHUNK; c++) {
        if (c == NCHUNK - 1) asm volatile("cp.async.wait_group 0;" ::: "memory");
        else                 asm volatile("cp.async.wait_group 1;" ::: "memory");
        __syncthreads();
        const uint32_t Ab = st[c % NSTAGE], Bb = Ab + A_BYTES;

        // STS A(c+1) from buf
        if (c + 1 < NCHUNK) {
            uint32_t dstA = st[(c + 1) % NSTAGE];
#pragma unroll
            for (int i = 0; i < 4; i++) sts16(dstA + aoff[i], buf[i]);
        }
        const bool pre = (c + 2 < NCHUNK);
        const float* xs = xrow0 + (c + 2) * BK;
        float4 r0a, r0b, r1a, r1b;
        if (pre) {   // first half of A(c+2)
            r0a = *(const float4*)(xs + goff[0]);
            r0b = *(const float4*)(xs + goff[0] + 4);
            r1a = *(const float4*)(xs + goff[1]);
            r1b = *(const float4*)(xs + goff[1] + 4);
            issueB(st[(c + 2) % NSTAGE], wrow0, c + 2, tid);
        }

#pragma unroll
        for (int kq = 0; kq < 4; kq++) {
            uint32_t a0[4], a1[4];
            {
                uint32_t qsel = (uint32_t)((2 * kq + qbA) ^ axor) << 4;
                ldsm4(a0, Ab + abase0 + qsel);
                ldsm4(a1, Ab + abase1 + qsel);
            }
            uint32_t qselB = (uint32_t)((2 * kq + qbB) ^ bxor) << 4;
#pragma unroll
            for (int g = 0; g < 4; g++) {
                if (g < NPAIR) {
                    uint32_t b[4];
                    ldsm4(b, Bb + bbase[g] + qselB);
                    if (warp_n == 0) {
                        mma16(acc[0][2 * g < NJ0 ? 2 * g : 0], a0, b[0], b[1]);
                        mma16(acc[1][2 * g < NJ0 ? 2 * g : 0], a1, b[0], b[1]);
                        if (2 * g + 1 < NJ0) {
                            mma16(acc[0][2 * g + 1], a0, b[2], b[3]);
                            mma16(acc[1][2 * g + 1], a1, b[2], b[3]);
                        }
                    } else {
                        if (2 * g < NJ1) {
                            mma16(acc[0][2 * g], a0, b[0], b[1]);
                            mma16(acc[1][2 * g], a1, b[0], b[1]);
                        }
                        if (2 * g + 1 < NJ1) {
                            mma16(acc[0][2 * g + 1], a0, b[2], b[3]);
                            mma16(acc[1][2 * g + 1], a1, b[2], b[3]);
                        }
                    }
                }
            }
            if (kq == 0 && pre) {   // cvt first half, load second half
                buf[0] = pack8(r0a, r0b);
                buf[1] = pack8(r1a, r1b);
                r0a = *(const float4*)(xs + goff[2]);
                r0b = *(const float4*)(xs + goff[2] + 4);
                r1a = *(const float4*)(xs + goff[3]);
                r1b = *(const float4*)(xs + goff[3] + 4);
            }
            if (kq == 2 && pre) {   // cvt second half
                buf[2] = pack8(r0a, r0b);
                buf[3] = pack8(r1a, r1b);
            }
        }
    }
    __syncthreads();

    // ---- epilogue ----
    float* sC = (float*)(sm + 1024);
    const int tr = lane >> 2, tc2 = (lane & 3) * 2;
#pragma unroll
    for (int mi = 0; mi < 2; mi++)
#pragma unroll
        for (int nj = 0; nj < NJ0; nj++)
            if (nj < NJ) {
                int r = warp_m * 32 + mi * 16 + tr;
                int cc = colbase + nj * 8 + tc2;
                *(float2*)&sC[r * LDC + cc]       = make_float2(acc[mi][nj][0], acc[mi][nj][1]);
                *(float2*)&sC[(r + 8) * LDC + cc] = make_float2(acc[mi][nj][2], acc[mi][nj][3]);
            }
    __syncthreads();

    float* outb = out + NS;
    const int jbase = nt * BNL;
    for (int e = tid; e < BM * LIVE; e += 256) {
        int row = e / LIVE, n = e - row * LIVE;
        int j = jbase + n;
        float v = sC[row * LDC + n] + sBias[n];
        size_t gr = row0 + row;
        if (j < 81) out[gr * 81 + j] = v;
        else        outb[gr * 324 + (j - 81)] = v;
    }
}

__global__ __launch_bounds__(256, 2) void k_main(const float* __restrict__ x,
                                                 float* __restrict__ out, int N) {
    extern __shared__ char sm[];
    const int nt = blockIdx.x;
    if (nt < 3) gemm_body<7, 6, 56, 104>(sm, x, out, N, nt);
    else        gemm_body<6, 6, 48, 93>(sm, x, out, N, nt);
}

// ---------------- launch ----------------
extern "C" void kernel_launch(void* const* d_in, const int* in_sizes, int n_in,
                              void* d_out, int out_size) {
    const float* x    = (const float*)d_in[0];
    const float* Wcls = (const float*)d_in[1];
    const float* bcls = (const float*)d_in[2];
    const float* Wsem = (const float*)d_in[3];
    const float* bsem = (const float*)d_in[4];
    const float* Wbb  = (const float*)d_in[5];
    const float* bbb  = (const float*)d_in[6];
    const float* semm = (const float*)d_in[7];
    float* out = (float*)d_out;
    int N = in_sizes[0] / DD;

    cudaFuncSetAttribute(k_main, cudaFuncAttributeMaxDynamicSharedMemorySize, SMEM_DYN);

    k_fold<<<dim3(4, 5), 256>>>(Wsem, bsem, semm);
    k_copy<<<NTILE * BNP, 256>>>(Wcls, bcls, Wbb, bbb);
    dim3 grid(NTILE, N / BM);
    k_main<<<grid, 256, SMEM_DYN>>>(x, out, N);
}

// round 12
// speedup vs baseline: 7.5391x; 1.3425x over previous
#include <cuda_runtime.h>
#include <cuda_fp16.h>
#include <cstdint>
#include <cstddef>

// ---------------- problem constants ----------------
#define DD     1024
#define PCOLS  405       // 1 + 80 + 324
#define NTILE  4
#define BNL    104       // live cols per tile
#define BNP    112       // padded rows per tile
#define NF     300
#define NMAX   65536
#define BM     128
#define BK     64        // fp16: 64 halves = 128B rows -> SW128 swizzle
#define NCHUNK (DD / BK) // 16
#define NSTAGE 3

#define A_BYTES  (BM * 128)              // 16384
#define B_BYTES  (BNP * 128)             // 14336
#define STAGE_SZ (A_BYTES + B_BYTES)     // 30720
#define SMEM_DYN (1024 + NSTAGE * STAGE_SZ)  // 93184 -> 2 CTAs/SM
#define LDC      120

// ---------------- device scratch ----------------
__device__ __half g_xh[(size_t)NMAX * DD];        // 128 MB fp16 x
__device__ __half g_Wh[(size_t)NTILE * BNP * DD];
__device__ float  g_bias[NTILE * BNP];

// ---------------- helpers ----------------
__device__ __forceinline__ uint32_t smem_u32(const void* p) {
    uint32_t a;
    asm("{ .reg .u64 t; cvta.to.shared.u64 t, %1; cvt.u32.u64 %0, t; }" : "=r"(a) : "l"(p));
    return a;
}
__device__ __forceinline__ void cpa16(uint32_t dst, const void* src) {
    asm volatile("cp.async.cg.shared.global [%0], [%1], 16;" :: "r"(dst), "l"(src));
}
__device__ __forceinline__ void ldsm4(uint32_t r[4], uint32_t addr) {
    asm volatile("ldmatrix.sync.aligned.m8n8.x4.shared.b16 {%0,%1,%2,%3}, [%4];"
        : "=r"(r[0]), "=r"(r[1]), "=r"(r[2]), "=r"(r[3]) : "r"(addr));
}
__device__ __forceinline__ void mma16(float d[4], const uint32_t a[4], uint32_t b0, uint32_t b1) {
    asm volatile(
        "mma.sync.aligned.m16n8k16.row.col.f32.f16.f16.f32 "
        "{%0,%1,%2,%3}, {%4,%5,%6,%7}, {%8,%9}, {%0,%1,%2,%3};"
        : "+f"(d[0]), "+f"(d[1]), "+f"(d[2]), "+f"(d[3])
        : "r"(a[0]), "r"(a[1]), "r"(a[2]), "r"(a[3]), "r"(b0), "r"(b1));
}
__device__ __forceinline__ uint4 pack8(float4 a, float4 b) {
    __half2 h0 = __floats2half2_rn(a.x, a.y);
    __half2 h1 = __floats2half2_rn(a.z, a.w);
    __half2 h2 = __floats2half2_rn(b.x, b.y);
    __half2 h3 = __floats2half2_rn(b.z, b.w);
    uint4 u;
    u.x = *reinterpret_cast<uint32_t*>(&h0);
    u.y = *reinterpret_cast<uint32_t*>(&h1);
    u.z = *reinterpret_cast<uint32_t*>(&h2);
    u.w = *reinterpret_cast<uint32_t*>(&h3);
    return u;
}

// ---------------- k_cvt: x fp32 -> fp16, streaming ----------------
__global__ void k_cvt(const float4* __restrict__ xi, int n8) {
    uint4* xo = reinterpret_cast<uint4*>(g_xh);
    int i = blockIdx.x * blockDim.x + threadIdx.x;   // one uint4 (8 halves) each
    if (i < n8) {
        float4 a = xi[2 * i], b = xi[2 * i + 1];
        xo[i] = pack8(a, b);
    }
}

// ---------------- k_fold: W_eff[80,1024] = (8*norm(semm)) @ Wsem, fp16 out ----------
// grid (8 colgroups x 20 rowgroups), 128 threads: 4 rows x 128 cols per CTA
__global__ void k_fold(const float* __restrict__ Wsem, const float* __restrict__ bsem,
                       const float* __restrict__ semm) {
    __shared__ float ssm[4 * NF];
    __shared__ float sscale[4];
    const int cg = blockIdx.x;        // 0..7 (128 cols)
    const int rg = blockIdx.y;        // 0..19 (4 rows)
    const int t = threadIdx.x, wid = t >> 5, lane = t & 31;
    const int r0 = rg * 4, c0 = cg * 128;

    {   // warp w -> norm of row w
        const float* src = semm + (size_t)(r0 + wid) * NF;
        float ss = 0.f;
        for (int f = lane; f < NF; f += 32) { float v = src[f]; ss += v * v; }
        for (int o = 16; o; o >>= 1) ss += __shfl_xor_sync(~0u, ss, o);
        if (lane == 0) sscale[wid] = 8.0f * rsqrtf(ss);
    }
    __syncthreads();
    for (int idx = t; idx < 4 * NF; idx += 128) {
        int ri = idx / NF, f = idx - ri * NF;
        ssm[ri * NF + f] = semm[(size_t)(r0 + ri) * NF + f] * sscale[ri];
    }
    __syncthreads();

    float acc[4] = {0.f, 0.f, 0.f, 0.f};
    const float* wp = Wsem + c0 + t;
#pragma unroll 10
    for (int f = 0; f < NF; f++) {
        float w = wp[(size_t)f * DD];
#pragma unroll
        for (int ri = 0; ri < 4; ri++) acc[ri] += ssm[ri * NF + f] * w;
    }
#pragma unroll
    for (int ri = 0; ri < 4; ri++)
        g_Wh[(size_t)(1 + r0 + ri) * DD + c0 + t] = __float2half_rn(acc[ri]);

    if (cg == 0) {   // warp w -> bias of row w
        float bb = 0.f;
        for (int f = lane; f < NF; f += 32) bb += ssm[wid * NF + f] * bsem[f];
        for (int o = 16; o; o >>= 1) bb += __shfl_xor_sync(~0u, bb, o);
        if (lane == 0) g_bias[1 + r0 + wid] = bb;
    }
}

// ---------------- k_copy: cls/bbox rows -> fp16, bias, padding ----------------
__global__ void k_copy(const float* __restrict__ Wcls, const float* __restrict__ bcls,
                       const float* __restrict__ Wbb,  const float* __restrict__ bbb) {
    const int p = blockIdx.x, t = threadIdx.x;
    const int tile = p / BNP, r = p - tile * BNP;
    const int j = tile * BNL + r;
    __half* wo = g_Wh + (size_t)p * DD;
    if (r >= BNL || j >= PCOLS) {
        for (int d = t; d < DD; d += 256) wo[d] = __float2half_rn(0.f);
        if (t == 0) g_bias[p] = 0.f;
    } else if (j == 0) {
        for (int d = t; d < DD; d += 256) wo[d] = __float2half_rn(Wcls[d]);
        if (t == 0) g_bias[p] = bcls[0];
    } else if (j <= 80) {
        // written by k_fold
    } else {
        const int i = j - 81;
        for (int d = t; d < DD; d += 256) wo[d] = __float2half_rn(Wbb[(size_t)i * DD + d]);
        if (t == 0) g_bias[p] = bbb[i];
    }
}

// ---------------- main GEMM: fp16 m16n8k16, all-cp.async ----------------
__device__ __forceinline__ void issue_stage(uint32_t sbase, const __half* __restrict__ xrow0,
                                            const __half* __restrict__ wrow0, int c, int tid) {
    const __half* xs = xrow0 + c * BK;
    const __half* ws = wrow0 + c * BK;
#pragma unroll
    for (int i = 0; i < 4; i++) {               // A: 128 rows x 8 quads = 1024
        int seg = tid + i * 256;
        int row = seg >> 3, q = seg & 7;
        cpa16(sbase + (uint32_t)(row * 128 + ((q ^ (row & 7)) << 4)),
              xs + (size_t)row * DD + q * 8);
    }
#pragma unroll
    for (int i = 0; i < 4; i++) {               // B: 112 rows x 8 quads = 896
        int seg = tid + i * 256;
        if (seg < BNP * 8) {
            int row = seg >> 3, q = seg & 7;
            cpa16(sbase + (uint32_t)(A_BYTES + row * 128 + ((q ^ (row & 7)) << 4)),
                  ws + (size_t)row * DD + q * 8);
        }
    }
    asm volatile("cp.async.commit_group;" ::: "memory");
}

template <int NJ0, int NJ1, int NB1, int LIVE>
__device__ __forceinline__ void gemm_body(char* sm, float* __restrict__ out, int N, int nt) {
    const int tid = threadIdx.x, wid = tid >> 5, lane = tid & 31;
    const int warp_m = wid & 3;
    const int warp_n = wid >> 2;
    const size_t row0 = (size_t)blockIdx.y * BM;
    const size_t NS = (size_t)N * 81;
    const int NJ = warp_n ? NJ1 : NJ0;
    const int NPAIR = warp_n ? ((NJ1 + 1) >> 1) : ((NJ0 + 1) >> 1);
    const int colbase = warp_n ? NB1 : 0;

    float* sBias = (float*)sm;
    for (int i = tid; i < BNP; i += 256) sBias[i] = g_bias[nt * BNP + i];

    uint32_t st[NSTAGE];
#pragma unroll
    for (int s = 0; s < NSTAGE; s++) st[s] = smem_u32(sm + 1024 + s * STAGE_SZ);

    const __half* xrow0 = g_xh + row0 * DD;
    const __half* wrow0 = g_Wh + (size_t)nt * BNP * DD;

    // ldsm addressing (verified fragment mapping from R11)
    const int rAr = warp_m * 32 + ((lane >> 3) & 1) * 8 + (lane & 7);
    const int qbA = lane >> 4;
    const uint32_t abase0 = (uint32_t)rAr * 128, abase1 = (uint32_t)(rAr + 16) * 128;
    const uint32_t axor = (uint32_t)(rAr & 7);
    const int rBr = colbase + (lane >> 4) * 8 + (lane & 7);
    const int qbB = (lane >> 3) & 1;
    uint32_t bbase[4];
#pragma unroll
    for (int g = 0; g < 4; g++) bbase[g] = (uint32_t)(rBr + g * 16) * 128;
    const uint32_t bxor = (uint32_t)(rBr & 7);

    float acc[2][NJ0][4];
#pragma unroll
    for (int mi = 0; mi < 2; mi++)
#pragma unroll
        for (int nj = 0; nj < NJ0; nj++)
#pragma unroll
            for (int e = 0; e < 4; e++) acc[mi][nj][e] = 0.f;

    issue_stage(st[0], xrow0, wrow0, 0, tid);
    issue_stage(st[1], xrow0, wrow0, 1, tid);

    for (int c = 0; c < NCHUNK; c++) {
        uint32_t Ab = st[c % NSTAGE], Bb = Ab + A_BYTES;
        if (c == NCHUNK - 1) asm volatile("cp.async.wait_group 0;" ::: "memory");
        else                 asm volatile("cp.async.wait_group 1;" ::: "memory");
        __syncthreads();
        if (c + 2 < NCHUNK)
            issue_stage(st[(c + 2) % NSTAGE], xrow0, wrow0, c + 2, tid);

#pragma unroll
        for (int kq = 0; kq < 4; kq++) {
            uint32_t a0[4], a1[4];
            uint32_t qsel = (uint32_t)((2 * kq + qbA) ^ axor) << 4;
            ldsm4(a0, Ab + abase0 + qsel);
            ldsm4(a1, Ab + abase1 + qsel);
            uint32_t qselB = (uint32_t)((2 * kq + qbB) ^ bxor) << 4;
            if (warp_n == 0) {
#pragma unroll
                for (int g = 0; g < 4; g++) {
                    if (g < (NJ0 + 1) / 2) {
                        uint32_t b[4];
                        ldsm4(b, Bb + bbase[g] + qselB);
                        if (2 * g < NJ0)     { mma16(acc[0][2 * g],     a0, b[0], b[1]);
                                               mma16(acc[1][2 * g],     a1, b[0], b[1]); }
                        if (2 * g + 1 < NJ0) { mma16(acc[0][2 * g + 1], a0, b[2], b[3]);
                                               mma16(acc[1][2 * g + 1], a1, b[2], b[3]); }
                    }
                }
            } else {
#pragma unroll
                for (int g = 0; g < 4; g++) {
                    if (g < (NJ1 + 1) / 2) {
                        uint32_t b[4];
                        ldsm4(b, Bb + bbase[g] + qselB);
                        if (2 * g < NJ1)     { mma16(acc[0][2 * g],     a0, b[0], b[1]);
                                               mma16(acc[1][2 * g],     a1, b[0], b[1]); }
                        if (2 * g + 1 < NJ1) { mma16(acc[0][2 * g + 1], a0, b[2], b[3]);
                                               mma16(acc[1][2 * g + 1], a1, b[2], b[3]); }
                    }
                }
            }
        }
    }
    __syncthreads();

    // ---- epilogue ----
    float* sC = (float*)(sm + 1024);
    const int tr = lane >> 2, tc2 = (lane & 3) * 2;
#pragma unroll
    for (int mi = 0; mi < 2; mi++)
#pragma unroll
        for (int nj = 0; nj < NJ0; nj++)
            if (nj < NJ) {
                int r = warp_m * 32 + mi * 16 + tr;
                int cc = colbase + nj * 8 + tc2;
                *(float2*)&sC[r * LDC + cc]       = make_float2(acc[mi][nj][0], acc[mi][nj][1]);
                *(float2*)&sC[(r + 8) * LDC + cc] = make_float2(acc[mi][nj][2], acc[mi][nj][3]);
            }
    __syncthreads();

    float* outb = out + NS;
    const int jbase = nt * BNL;
    for (int e = tid; e < BM * LIVE; e += 256) {
        int row = e / LIVE, n = e - row * LIVE;
        int j = jbase + n;
        float v = sC[row * LDC + n] + sBias[n];
        size_t gr = row0 + row;
        if (j < 81) out[gr * 81 + j] = v;
        else        outb[gr * 324 + (j - 81)] = v;
    }
}

__global__ __launch_bounds__(256, 2) void k_main(float* __restrict__ out, int N) {
    extern __shared__ char sm[];
    const int nt = blockIdx.x;
    if (nt < 3) gemm_body<7, 6, 56, 104>(sm, out, N, nt);
    else        gemm_body<6, 6, 48, 93>(sm, out, N, nt);
}

// ---------------- launch ----------------
extern "C" void kernel_launch(void* const* d_in, const int* in_sizes, int n_in,
                              void* d_out, int out_size) {
    const float* x    = (const float*)d_in[0];
    const float* Wcls = (const float*)d_in[1];
    const float* bcls = (const float*)d_in[2];
    const float* Wsem = (const float*)d_in[3];
    const float* bsem = (const float*)d_in[4];
    const float* Wbb  = (const float*)d_in[5];
    const float* bbb  = (const float*)d_in[6];
    const float* semm = (const float*)d_in[7];
    float* out = (float*)d_out;
    int N = in_sizes[0] / DD;

    cudaFuncSetAttribute(k_main, cudaFuncAttributeMaxDynamicSharedMemorySize, SMEM_DYN);

    int n8 = N * DD / 8;
    k_cvt<<<(n8 + 255) / 256, 256>>>((const float4*)x, n8);
    k_fold<<<dim3(8, 20), 128>>>(Wsem, bsem, semm);
    k_copy<<<NTILE * BNP, 256>>>(Wcls, bcls, Wbb, bbb);
    dim3 grid(NTILE, N / BM);
    k_main<<<grid, 256, SMEM_DYN>>>(out, N);
}